// round 14
// baseline (speedup 1.0000x reference)
#include <cuda_runtime.h>
#include <math.h>

#define BN_EPS 1e-5f

typedef unsigned long long ull;

__device__ __forceinline__ ull pk2(float lo, float hi) {
    ull r; asm("mov.b64 %0, {%1, %2};" : "=l"(r) : "f"(lo), "f"(hi)); return r;
}
__device__ __forceinline__ float2 upk2(ull v) {
    float2 f; asm("mov.b64 {%0, %1}, %2;" : "=f"(f.x), "=f"(f.y) : "l"(v)); return f;
}
__device__ __forceinline__ ull ff2(ull a, ull b, ull c) {
    ull d; asm("fma.rn.f32x2 %0, %1, %2, %3;" : "=l"(d) : "l"(a), "l"(b), "l"(c)); return d;
}

// ---------------- scratch (device globals; no allocation allowed) ----------------
__device__ float g_h1[4096 * 32 * 16 * 16];   // 128 MB  [B,32,16,16]
__device__ float g_h2[4096 * 64 * 8 * 8];     //  64 MB  [B,64,8,8]
__device__ float g_feat[4096 * 128];          //   2 MB  [B,128]
__device__ ull   g_pw1[32 * 27];              // conv1 weights, duplicated f32x2
__device__ ull   g_pw2[64 * 288];             // conv2 weights, duplicated f32x2
__device__ ull   g_pw3[128 * 576];            // conv3 weights, duplicated f32x2

// =============================================================================
// Prep: duplicate-pack all conv weights (w -> (w,w) as ull).
// =============================================================================
__global__ __launch_bounds__(256) void pack_weights(
    const float* __restrict__ w1, const float* __restrict__ w2,
    const float* __restrict__ w3)
{
    int i = blockIdx.x * 256 + threadIdx.x;
    if (i < 32 * 27)  { float v = w1[i]; g_pw1[i] = pk2(v, v); }
    if (i < 64 * 288) { float v = w2[i]; g_pw2[i] = pk2(v, v); }
    if (i < 128 * 576) { float v = w3[i]; g_pw3[i] = pk2(v, v); }
}

// =============================================================================
// Stage 1: conv(3->32) + BN + ReLU + pool. grid=B*2 (16 oc), block=128.
// Warp = row-quarter h (out rows 8h..8h+7). Lane = ocg(8, 2 oc) x cp(4).
// 4 col-iterations of 8 cols. Input bordered rows [0,v0..v31,0] stride 36;
// L,R aligned LDS.64, V = pk2(L.y,R.x). ull weights (stride 29, bank-clean).
// One barrier total.
// =============================================================================
__global__ __launch_bounds__(128) void conv1_kernel(
    const float* __restrict__ x,
    const float* __restrict__ bias,
    const float* __restrict__ gam,
    const float* __restrict__ bet,
    const float* __restrict__ mean,
    const float* __restrict__ var)
{
    __shared__ float s_in[3 * 32 * 36];   // 13.8 KB: ch*1152 + r*36 + [0|1..32|33]
    __shared__ ull s_w[16 * 29];          // 3.7 KB

    const int b = blockIdx.x >> 1;
    const int och = (blockIdx.x & 1) * 16;
    const int tid = threadIdx.x;
    const int h = tid >> 5;              // row quarter
    const int lane = tid & 31;
    const int ocg = lane >> 2;           // 0..7
    const int cp = lane & 3;             // col pair within 8-col strip
    const int oc0l = ocg * 2;
    const int oc0 = och + oc0l;

    // BN prefetch for this thread's 2 ocs
    float inv0 = gam[oc0] * rsqrtf(var[oc0] + BN_EPS);
    float sh0 = (bias[oc0] - mean[oc0]) * inv0 + bet[oc0];
    float inv1 = gam[oc0 + 1] * rsqrtf(var[oc0 + 1] + BN_EPS);
    float sh1 = (bias[oc0 + 1] - mean[oc0 + 1]) * inv1 + bet[oc0 + 1];

    // borders
    for (int i = tid; i < 192; i += 128) {
        int ch = i / 64, r = (i & 63) >> 1, side = i & 1;
        s_in[ch * 1152 + r * 36 + side * 33] = 0.f;
    }
    // input [3,32,32]
    {
        const float4* src = (const float4*)(x + (size_t)b * 3072);
        #pragma unroll
        for (int i = 0; i < 6; i++) {
            int idx4 = tid + i * 128;          // 0..767
            float4 v = src[idx4];
            int ch = idx4 >> 8, rem = idx4 & 255;
            int r = rem >> 3, c4 = (rem & 7) * 4;
            float* row = &s_in[ch * 1152 + r * 36 + 1 + c4];
            row[0] = v.x; row[1] = v.y; row[2] = v.z; row[3] = v.w;
        }
    }
    // weights: 16 oc x 27 ull
    for (int i = tid; i < 432; i += 128) {
        int o = i / 27, j = i % 27;
        s_w[o * 29 + j] = g_pw1[(och + o) * 27 + j];
    }
    __syncthreads();

    float* ob = g_h1 + (size_t)b * 8192;

    #pragma unroll 1
    for (int iter = 0; iter < 4; iter++) {
        ull acc0[8], acc1[8];
        #pragma unroll
        for (int i = 0; i < 8; i++) { acc0[i] = 0ull; acc1[i] = 0ull; }

        #pragma unroll
        for (int ic = 0; ic < 3; ic++) {
            const ull* w0p = &s_w[oc0l * 29 + ic * 9];
            const ull* w1p = w0p + 29;
            ull W0[9], W1[9];
            #pragma unroll
            for (int k = 0; k < 9; k++) { W0[k] = w0p[k]; W1[k] = w1p[k]; }

            const float* rb = &s_in[ic * 1152 + iter * 8 + 2 * cp];
            #pragma unroll
            for (int ri = 0; ri < 10; ri++) {
                int r = 8 * h - 1 + ri;
                if (r >= 0 && r <= 31) {
                    const float* rp = rb + r * 36;
                    ull L = *(const ull*)rp;
                    ull R = *(const ull*)(rp + 2);
                    float2 Lf = upk2(L), Rf = upk2(R);
                    ull V = pk2(Lf.y, Rf.x);
                    const int t = ri - 1;       // local out row
                    if (t >= 1) {
                        acc0[t - 1] = ff2(W0[6], L, ff2(W0[7], V, ff2(W0[8], R, acc0[t - 1])));
                        acc1[t - 1] = ff2(W1[6], L, ff2(W1[7], V, ff2(W1[8], R, acc1[t - 1])));
                    }
                    if (t >= 0 && t <= 7) {
                        acc0[t] = ff2(W0[3], L, ff2(W0[4], V, ff2(W0[5], R, acc0[t])));
                        acc1[t] = ff2(W1[3], L, ff2(W1[4], V, ff2(W1[5], R, acc1[t])));
                    }
                    if (t <= 6) {
                        acc0[t + 1] = ff2(W0[0], L, ff2(W0[1], V, ff2(W0[2], R, acc0[t + 1])));
                        acc1[t + 1] = ff2(W1[0], L, ff2(W1[1], V, ff2(W1[2], R, acc1[t + 1])));
                    }
                }
            }
        }

        // BN + ReLU + 2x2 pool; pooled rows 4h..4h+3, pooled col iter*4+cp
        #pragma unroll
        for (int j = 0; j < 4; j++) {
            float2 a = upk2(acc0[2 * j]);
            float2 c = upk2(acc0[2 * j + 1]);
            float v00 = fmaxf(fmaf(a.x, inv0, sh0), 0.f);
            float v01 = fmaxf(fmaf(a.y, inv0, sh0), 0.f);
            float v10 = fmaxf(fmaf(c.x, inv0, sh0), 0.f);
            float v11 = fmaxf(fmaf(c.y, inv0, sh0), 0.f);
            ob[oc0 * 256 + (4 * h + j) * 16 + iter * 4 + cp] =
                fmaxf(fmaxf(v00, v01), fmaxf(v10, v11));
            float2 a1 = upk2(acc1[2 * j]);
            float2 c1 = upk2(acc1[2 * j + 1]);
            float w00 = fmaxf(fmaf(a1.x, inv1, sh1), 0.f);
            float w01 = fmaxf(fmaf(a1.y, inv1, sh1), 0.f);
            float w10 = fmaxf(fmaf(c1.x, inv1, sh1), 0.f);
            float w11 = fmaxf(fmaf(c1.y, inv1, sh1), 0.f);
            ob[(oc0 + 1) * 256 + (4 * h + j) * 16 + iter * 4 + cp] =
                fmaxf(fmaxf(w00, w01), fmaxf(w10, w11));
        }
    }
}

// =============================================================================
// Stage 2: conv(32->64) + BN + ReLU + pool. grid=B*4, block=128. (R13 version)
// =============================================================================
__global__ __launch_bounds__(128) void conv2_kernel(
    const float* __restrict__ bias,
    const float* __restrict__ gam,
    const float* __restrict__ bet,
    const float* __restrict__ mean,
    const float* __restrict__ var)
{
    __shared__ float s_in[8 * 16 * 20];   // 10.2 KB
    __shared__ ull   s_w[16 * 73];        // 9.3 KB (stride 73: bank-clean)

    const int b = blockIdx.x >> 2;
    const int oc_base = (blockIdx.x & 3) * 16;
    const int tid = threadIdx.x;
    const int warp = tid >> 5;
    const int lane = tid & 31;
    const int cp = lane & 7;
    const int ocg = lane >> 3;
    const int h = warp >> 1;
    const int st = warp & 1;
    const int oc0l = st * 8 + ocg * 2;
    const int oc0 = oc_base + oc0l;

    {
        int ic = tid >> 4, r = tid & 15;
        s_in[ic * 320 + r * 20] = 0.f;
        s_in[ic * 320 + r * 20 + 17] = 0.f;
    }

    ull acc0[8], acc1[8];
    #pragma unroll
    for (int i = 0; i < 8; i++) { acc0[i] = 0ull; acc1[i] = 0ull; }

    for (int pass = 0; pass < 4; pass++) {
        __syncthreads();
        {
            const float4* src = (const float4*)(g_h1 + (size_t)b * 8192 + pass * 2048);
            #pragma unroll
            for (int i = 0; i < 4; i++) {
                int idx4 = tid + i * 128;
                float4 v = src[idx4];
                int ic = idx4 >> 6;
                int r = (idx4 >> 2) & 15;
                int c4 = (idx4 & 3) * 4;
                float* row = &s_in[ic * 320 + r * 20];
                row[1 + c4] = v.x; row[2 + c4] = v.y;
                row[3 + c4] = v.z; row[4 + c4] = v.w;
            }
        }
        for (int i = tid; i < 16 * 72; i += 128) {
            int o = i / 72, j = i % 72;
            s_w[o * 73 + j] = g_pw2[(oc_base + o) * 288 + pass * 72 + j];
        }
        __syncthreads();

        #pragma unroll 1
        for (int ici = 0; ici < 8; ici++) {
            const ull* w0p = &s_w[oc0l * 73 + ici * 9];
            const ull* w1p = w0p + 73;
            ull W0[9], W1[9];
            #pragma unroll
            for (int k = 0; k < 9; k++) { W0[k] = w0p[k]; W1[k] = w1p[k]; }

            const float* rb = &s_in[ici * 320 + 2 * cp];
            if (h == 0) {
                #pragma unroll
                for (int r = 0; r < 9; r++) {
                    ull L = *(const ull*)(rb + r * 20);
                    ull R = *(const ull*)(rb + r * 20 + 2);
                    float2 Lf = upk2(L), Rf = upk2(R);
                    ull V = pk2(Lf.y, Rf.x);
                    if (r >= 1) {
                        acc0[r - 1] = ff2(W0[6], L, ff2(W0[7], V, ff2(W0[8], R, acc0[r - 1])));
                        acc1[r - 1] = ff2(W1[6], L, ff2(W1[7], V, ff2(W1[8], R, acc1[r - 1])));
                    }
                    if (r <= 7) {
                        acc0[r] = ff2(W0[3], L, ff2(W0[4], V, ff2(W0[5], R, acc0[r])));
                        acc1[r] = ff2(W1[3], L, ff2(W1[4], V, ff2(W1[5], R, acc1[r])));
                    }
                    if (r <= 6) {
                        acc0[r + 1] = ff2(W0[0], L, ff2(W0[1], V, ff2(W0[2], R, acc0[r + 1])));
                        acc1[r + 1] = ff2(W1[0], L, ff2(W1[1], V, ff2(W1[2], R, acc1[r + 1])));
                    }
                }
            } else {
                #pragma unroll
                for (int ri = 0; ri < 9; ri++) {
                    const int r = 7 + ri;
                    const int t = ri - 1;
                    ull L = *(const ull*)(rb + r * 20);
                    ull R = *(const ull*)(rb + r * 20 + 2);
                    float2 Lf = upk2(L), Rf = upk2(R);
                    ull V = pk2(Lf.y, Rf.x);
                    if (t >= 1) {
                        acc0[t - 1] = ff2(W0[6], L, ff2(W0[7], V, ff2(W0[8], R, acc0[t - 1])));
                        acc1[t - 1] = ff2(W1[6], L, ff2(W1[7], V, ff2(W1[8], R, acc1[t - 1])));
                    }
                    if (t >= 0 && t <= 7) {
                        acc0[t] = ff2(W0[3], L, ff2(W0[4], V, ff2(W0[5], R, acc0[t])));
                        acc1[t] = ff2(W1[3], L, ff2(W1[4], V, ff2(W1[5], R, acc1[t])));
                    }
                    if (t <= 6) {
                        acc0[t + 1] = ff2(W0[0], L, ff2(W0[1], V, ff2(W0[2], R, acc0[t + 1])));
                        acc1[t + 1] = ff2(W1[0], L, ff2(W1[1], V, ff2(W1[2], R, acc1[t + 1])));
                    }
                }
            }
        }
    }

    #pragma unroll
    for (int k = 0; k < 2; k++) {
        const int oc = oc0 + k;
        const ull* ac = k ? acc1 : acc0;
        float inv = gam[oc] * rsqrtf(var[oc] + BN_EPS);
        float sh = (bias[oc] - mean[oc]) * inv + bet[oc];
        float* ob = g_h2 + (size_t)b * 4096 + (size_t)oc * 64 + cp;
        #pragma unroll
        for (int j = 0; j < 4; j++) {
            float2 a = upk2(ac[2 * j]);
            float2 c = upk2(ac[2 * j + 1]);
            float v00 = fmaxf(fmaf(a.x, inv, sh), 0.f);
            float v01 = fmaxf(fmaf(a.y, inv, sh), 0.f);
            float v10 = fmaxf(fmaf(c.x, inv, sh), 0.f);
            float v11 = fmaxf(fmaf(c.y, inv, sh), 0.f);
            ob[(h * 4 + j) * 8] = fmaxf(fmaxf(v00, v01), fmaxf(v10, v11));
        }
    }
}

// =============================================================================
// Stage 3: conv(64->128) + BN + ReLU + pool + avgpool. grid=B*4 (32 oc/block),
// block=128. Warp = row-half h x oc-set s; lane = ocg(8, 2 oc) x cp(4).
// Thread: 2 oc x 4 out-rows x 1 col-pair (8 ull accs). Input single bordered
// copy stride 12, 2 passes of 32 ic; ull weights (stride 73) in 4 sub-stages
// of 8 ic per pass. 31 KB smem -> 7 blocks/SM.
// =============================================================================
__global__ __launch_bounds__(128) void conv3_kernel(
    const float* __restrict__ bias,
    const float* __restrict__ gam,
    const float* __restrict__ bet,
    const float* __restrict__ mean,
    const float* __restrict__ var)
{
    __shared__ float s_in[32 * 96];    // 12.3 KB: icl*96 + r*12 + [0|1..8|9]
    __shared__ ull   s_w[32 * 73];     // 18.7 KB (stride 73: bank-clean)
    __shared__ float s_red[4][16];

    const int b = blockIdx.x >> 2;
    const int och = (blockIdx.x & 3) * 32;
    const int tid = threadIdx.x;
    const int warp = tid >> 5;
    const int lane = tid & 31;
    const int h = warp >> 1;             // row half
    const int s = warp & 1;              // oc set
    const int ocg = lane >> 2;           // 0..7
    const int cp = lane & 3;             // col pair
    const int oc0l = s * 16 + ocg * 2;   // 0..30 even
    const int oc0 = och + oc0l;

    float inv0 = gam[oc0] * rsqrtf(var[oc0] + BN_EPS);
    float sh0 = (bias[oc0] - mean[oc0]) * inv0 + bet[oc0];
    float inv1 = gam[oc0 + 1] * rsqrtf(var[oc0 + 1] + BN_EPS);
    float sh1 = (bias[oc0 + 1] - mean[oc0 + 1]) * inv1 + bet[oc0 + 1];

    // borders (stages write cols 1..8 only; set once)
    for (int i = tid; i < 512; i += 128) {
        int ic = i >> 4, r = (i >> 1) & 7, side = i & 1;
        s_in[ic * 96 + r * 12 + side * 9] = 0.f;
    }

    ull acc0[4], acc1[4];
    #pragma unroll
    for (int i = 0; i < 4; i++) { acc0[i] = 0ull; acc1[i] = 0ull; }

    for (int pass = 0; pass < 2; pass++) {
        for (int q = 0; q < 4; q++) {
            __syncthreads();   // prior s_w/s_in reads done (and borders at start)
            if (q == 0) {
                const float4* src = (const float4*)(g_h2 + (size_t)b * 4096 + pass * 2048);
                #pragma unroll
                for (int i = 0; i < 4; i++) {
                    int idx4 = tid + i * 128;           // 0..511
                    float4 v = src[idx4];
                    int ic = idx4 >> 4;                 // 0..31 local
                    int r = (idx4 >> 1) & 7;
                    int c4 = (idx4 & 1) * 4;
                    float* row = &s_in[ic * 96 + r * 12 + 1 + c4];
                    row[0] = v.x; row[1] = v.y; row[2] = v.z; row[3] = v.w;
                }
            }
            // stage 8 ic of packed weights: 32 oc x 72 ull
            for (int i = tid; i < 2304; i += 128) {
                int o = i / 72, j = i % 72;
                s_w[o * 73 + j] =
                    g_pw3[(size_t)(och + o) * 576 + (pass * 32 + q * 8) * 9 + j];
            }
            __syncthreads();

            #pragma unroll 1
            for (int ici = 0; ici < 8; ici++) {
                const int icl = q * 8 + ici;           // local ic 0..31
                const ull* w0p = &s_w[oc0l * 73 + ici * 9];
                const ull* w1p = w0p + 73;
                ull W0[9], W1[9];
                #pragma unroll
                for (int k = 0; k < 9; k++) { W0[k] = w0p[k]; W1[k] = w1p[k]; }

                const float* rb = &s_in[icl * 96 + 2 * cp];
                #pragma unroll
                for (int ri = 0; ri < 6; ri++) {
                    int r = 4 * h - 1 + ri;
                    if (r >= 0 && r <= 7) {
                        const float* rp = rb + r * 12;
                        ull L = *(const ull*)rp;
                        ull R = *(const ull*)(rp + 2);
                        float2 Lf = upk2(L), Rf = upk2(R);
                        ull V = pk2(Lf.y, Rf.x);
                        const int t = ri - 1;          // local out row
                        if (t >= 1) {
                            acc0[t - 1] = ff2(W0[6], L, ff2(W0[7], V, ff2(W0[8], R, acc0[t - 1])));
                            acc1[t - 1] = ff2(W1[6], L, ff2(W1[7], V, ff2(W1[8], R, acc1[t - 1])));
                        }
                        if (t >= 0 && t <= 3) {
                            acc0[t] = ff2(W0[3], L, ff2(W0[4], V, ff2(W0[5], R, acc0[t])));
                            acc1[t] = ff2(W1[3], L, ff2(W1[4], V, ff2(W1[5], R, acc1[t])));
                        }
                        if (t <= 2) {
                            acc0[t + 1] = ff2(W0[0], L, ff2(W0[1], V, ff2(W0[2], R, acc0[t + 1])));
                            acc1[t + 1] = ff2(W1[0], L, ff2(W1[1], V, ff2(W1[2], R, acc1[t + 1])));
                        }
                    }
                }
            }
        }
    }

    // BN + ReLU + 2x2 pool + partial avg (2 pooled rows x 1 pooled col)
    float part0 = 0.f, part1 = 0.f;
    #pragma unroll
    for (int j = 0; j < 2; j++) {
        float2 a = upk2(acc0[2 * j]);
        float2 c = upk2(acc0[2 * j + 1]);
        part0 += fmaxf(fmaxf(fmaxf(fmaf(a.x, inv0, sh0), 0.f),
                             fmaxf(fmaf(a.y, inv0, sh0), 0.f)),
                       fmaxf(fmaxf(fmaf(c.x, inv0, sh0), 0.f),
                             fmaxf(fmaf(c.y, inv0, sh0), 0.f)));
        float2 a1 = upk2(acc1[2 * j]);
        float2 c1 = upk2(acc1[2 * j + 1]);
        part1 += fmaxf(fmaxf(fmaxf(fmaf(a1.x, inv1, sh1), 0.f),
                             fmaxf(fmaf(a1.y, inv1, sh1), 0.f)),
                       fmaxf(fmaxf(fmaf(c1.x, inv1, sh1), 0.f),
                             fmaxf(fmaf(c1.y, inv1, sh1), 0.f)));
    }
    part0 += __shfl_down_sync(0xffffffffu, part0, 2, 4);
    part0 += __shfl_down_sync(0xffffffffu, part0, 1, 4);
    part1 += __shfl_down_sync(0xffffffffu, part1, 2, 4);
    part1 += __shfl_down_sync(0xffffffffu, part1, 1, 4);
    __syncthreads();   // s_w reads done before s_red aliasing? (separate array; just order)
    if (cp == 0) {
        s_red[warp][ocg * 2] = part0;
        s_red[warp][ocg * 2 + 1] = part1;
    }
    __syncthreads();
    if (tid < 32) {
        int s2 = tid >> 4, ol = tid & 15;
        float sum = s_red[s2][ol] + s_red[s2 + 2][ol];
        g_feat[(size_t)b * 128 + och + s2 * 16 + ol] = sum * (1.f / 16.f);
    }
}

// =============================================================================
// Stage 4: gate (top-2 softmax) + top-2 expert MLPs, fused. (unchanged, 55us)
// =============================================================================
__global__ __launch_bounds__(256) void moe_kernel(
    const float* __restrict__ w1,   // [8,128,64]
    const float* __restrict__ b1,   // [8,64]
    const float* __restrict__ w2,   // [8,64,10]
    const float* __restrict__ b2,   // [8,10]
    const float* __restrict__ gw,   // [128,8]
    const float* __restrict__ gb,   // [8]
    float* __restrict__ out, int B)
{
    __shared__ float s_feat[8][128];
    __shared__ float s_h[8][64];
    __shared__ float s_log[8][8];

    const int warp = threadIdx.x >> 5;
    const int lane = threadIdx.x & 31;
    const int s = blockIdx.x * 8 + warp;
    if (s >= B) return;

    for (int i = lane; i < 128; i += 32) s_feat[warp][i] = g_feat[(size_t)s * 128 + i];
    __syncwarp();

    if (lane < 8) {
        float a = gb[lane];
        for (int f = 0; f < 128; f++) a += s_feat[warp][f] * gw[f * 8 + lane];
        s_log[warp][lane] = a;
    }
    __syncwarp();

    float lg[8];
    #pragma unroll
    for (int e = 0; e < 8; e++) lg[e] = s_log[warp][e];
    int i0 = 0; float v0 = lg[0];
    #pragma unroll
    for (int e = 1; e < 8; e++) if (lg[e] > v0) { v0 = lg[e]; i0 = e; }
    int i1 = -1; float v1 = -3.402823466e38f;
    #pragma unroll
    for (int e = 0; e < 8; e++) if (e != i0 && lg[e] > v1) { v1 = lg[e]; i1 = e; }
    float e1 = expf(v1 - v0);
    float invs = 1.f / (1.f + e1);
    float wts[2] = { invs, e1 * invs };
    int eidx[2] = { i0, i1 };

    float outk = 0.f;
    for (int t = 0; t < 2; t++) {
        const int e = eidx[t];
        const float* w1e = w1 + (size_t)e * 128 * 64;
        float h0 = b1[e * 64 + lane];
        float h1v = b1[e * 64 + lane + 32];
        for (int f = 0; f < 128; f++) {
            float fv = s_feat[warp][f];
            h0  += fv * w1e[f * 64 + lane];
            h1v += fv * w1e[f * 64 + lane + 32];
        }
        s_h[warp][lane] = fmaxf(h0, 0.f);
        s_h[warp][lane + 32] = fmaxf(h1v, 0.f);
        __syncwarp();
        if (lane < 10) {
            const float* w2e = w2 + e * 640;
            float o = b2[e * 10 + lane];
            for (int j = 0; j < 64; j++) o += s_h[warp][j] * w2e[j * 10 + lane];
            outk += wts[t] * o;
        }
        __syncwarp();
    }
    if (lane < 10) out[(size_t)s * 10 + lane] = outk;
}

// =============================================================================
extern "C" void kernel_launch(void* const* d_in, const int* in_sizes, int n_in,
                              void* d_out, int out_size)
{
    const float* x       = (const float*)d_in[0];
    const float* c1w     = (const float*)d_in[1];
    const float* c1b     = (const float*)d_in[2];
    const float* bn1g    = (const float*)d_in[3];
    const float* bn1b    = (const float*)d_in[4];
    const float* bn1m    = (const float*)d_in[5];
    const float* bn1v    = (const float*)d_in[6];
    const float* c2w     = (const float*)d_in[7];
    const float* c2b     = (const float*)d_in[8];
    const float* bn2g    = (const float*)d_in[9];
    const float* bn2b    = (const float*)d_in[10];
    const float* bn2m    = (const float*)d_in[11];
    const float* bn2v    = (const float*)d_in[12];
    const float* c3w     = (const float*)d_in[13];
    const float* c3b     = (const float*)d_in[14];
    const float* bn3g    = (const float*)d_in[15];
    const float* bn3b    = (const float*)d_in[16];
    const float* bn3m    = (const float*)d_in[17];
    const float* bn3v    = (const float*)d_in[18];
    const float* w1      = (const float*)d_in[19];
    const float* b1      = (const float*)d_in[20];
    const float* w2      = (const float*)d_in[21];
    const float* b2      = (const float*)d_in[22];
    const float* gate_w  = (const float*)d_in[23];
    const float* gate_b  = (const float*)d_in[24];

    int B = in_sizes[0] / (3 * 32 * 32);
    if (B > 4096) B = 4096;

    // pack kernel doubles as launch-slot shifter: profiled slot = conv3
    pack_weights<<<288, 256>>>(c1w, c2w, c3w);
    conv1_kernel<<<B * 2, 128>>>(x, c1b, bn1g, bn1b, bn1m, bn1v);
    conv2_kernel<<<B * 4, 128>>>(c2b, bn2g, bn2b, bn2m, bn2v);
    conv3_kernel<<<B * 4, 128>>>(c3b, bn3g, bn3b, bn3m, bn3v);
    moe_kernel<<<(B + 7) / 8, 256>>>(w1, b1, w2, b2, gate_w, gate_b, (float*)d_out, B);
}

// round 17
// speedup vs baseline: 1.1999x; 1.1999x over previous
#include <cuda_runtime.h>
#include <math.h>

#define BN_EPS 1e-5f

typedef unsigned long long ull;

__device__ __forceinline__ ull pk2(float lo, float hi) {
    ull r; asm("mov.b64 %0, {%1, %2};" : "=l"(r) : "f"(lo), "f"(hi)); return r;
}
__device__ __forceinline__ float2 upk2(ull v) {
    float2 f; asm("mov.b64 {%0, %1}, %2;" : "=f"(f.x), "=f"(f.y) : "l"(v)); return f;
}
__device__ __forceinline__ ull ff2(ull a, ull b, ull c) {
    ull d; asm("fma.rn.f32x2 %0, %1, %2, %3;" : "=l"(d) : "l"(a), "l"(b), "l"(c)); return d;
}

// ---------------- scratch (device globals; no allocation allowed) ----------------
__device__ float g_h1[4096 * 32 * 16 * 16];   // 128 MB  [B,32,16,16]
__device__ float g_h2[4096 * 64 * 8 * 8];     //  64 MB  [B,64,8,8]
__device__ float g_feat[4096 * 128];          //   2 MB  [B,128]
__device__ ull   g_pw1[32 * 27];              // conv1 weights, duplicated f32x2
__device__ ull   g_pw2[64 * 288];             // conv2 weights, duplicated f32x2

// =============================================================================
// Prep: duplicate-pack conv1/conv2 weights (w -> (w,w) as ull).
// =============================================================================
__global__ __launch_bounds__(256) void prep_pack_kernel(
    const float* __restrict__ w1, const float* __restrict__ w2)
{
    int i = blockIdx.x * 256 + threadIdx.x;
    if (i < 32 * 27)  { float v = w1[i]; g_pw1[i] = pk2(v, v); }
    if (i < 64 * 288) { float v = w2[i]; g_pw2[i] = pk2(v, v); }
}

// =============================================================================
// Stage 1 (R14 version): conv(3->32) + BN + ReLU + pool. grid=B*2, block=128.
// Warp = row-quarter h. Lane = ocg(8, 2 oc) x cp(4). One barrier total.
// =============================================================================
__global__ __launch_bounds__(128) void conv1_kernel(
    const float* __restrict__ x,
    const float* __restrict__ bias,
    const float* __restrict__ gam,
    const float* __restrict__ bet,
    const float* __restrict__ mean,
    const float* __restrict__ var)
{
    __shared__ float s_in[3 * 32 * 36];   // 13.8 KB: ch*1152 + r*36 + [0|1..32|33]
    __shared__ ull s_w[16 * 29];          // 3.7 KB

    const int b = blockIdx.x >> 1;
    const int och = (blockIdx.x & 1) * 16;
    const int tid = threadIdx.x;
    const int h = tid >> 5;              // row quarter
    const int lane = tid & 31;
    const int ocg = lane >> 2;           // 0..7
    const int cp = lane & 3;             // col pair within 8-col strip
    const int oc0l = ocg * 2;
    const int oc0 = och + oc0l;

    for (int i = tid; i < 192; i += 128) {
        int ch = i / 64, r = (i & 63) >> 1, side = i & 1;
        s_in[ch * 1152 + r * 36 + side * 33] = 0.f;
    }
    {
        const float4* src = (const float4*)(x + (size_t)b * 3072);
        #pragma unroll
        for (int i = 0; i < 6; i++) {
            int idx4 = tid + i * 128;          // 0..767
            float4 v = src[idx4];
            int ch = idx4 >> 8, rem = idx4 & 255;
            int r = rem >> 3, c4 = (rem & 7) * 4;
            float* row = &s_in[ch * 1152 + r * 36 + 1 + c4];
            row[0] = v.x; row[1] = v.y; row[2] = v.z; row[3] = v.w;
        }
    }
    for (int i = tid; i < 432; i += 128) {
        int o = i / 27, j = i % 27;
        s_w[o * 29 + j] = g_pw1[(och + o) * 27 + j];
    }

    float inv0 = gam[oc0] * rsqrtf(var[oc0] + BN_EPS);
    float sh0 = (bias[oc0] - mean[oc0]) * inv0 + bet[oc0];
    float inv1 = gam[oc0 + 1] * rsqrtf(var[oc0 + 1] + BN_EPS);
    float sh1 = (bias[oc0 + 1] - mean[oc0 + 1]) * inv1 + bet[oc0 + 1];
    __syncthreads();

    float* ob = g_h1 + (size_t)b * 8192;

    #pragma unroll 1
    for (int iter = 0; iter < 4; iter++) {
        ull acc0[8], acc1[8];
        #pragma unroll
        for (int i = 0; i < 8; i++) { acc0[i] = 0ull; acc1[i] = 0ull; }

        #pragma unroll
        for (int ic = 0; ic < 3; ic++) {
            const ull* w0p = &s_w[oc0l * 29 + ic * 9];
            const ull* w1p = w0p + 29;
            ull W0[9], W1[9];
            #pragma unroll
            for (int k = 0; k < 9; k++) { W0[k] = w0p[k]; W1[k] = w1p[k]; }

            const float* rb = &s_in[ic * 1152 + iter * 8 + 2 * cp];
            #pragma unroll
            for (int ri = 0; ri < 10; ri++) {
                int r = 8 * h - 1 + ri;
                if (r >= 0 && r <= 31) {
                    const float* rp = rb + r * 36;
                    ull L = *(const ull*)rp;
                    ull R = *(const ull*)(rp + 2);
                    float2 Lf = upk2(L), Rf = upk2(R);
                    ull V = pk2(Lf.y, Rf.x);
                    const int t = ri - 1;       // local out row
                    if (t >= 1) {
                        acc0[t - 1] = ff2(W0[6], L, ff2(W0[7], V, ff2(W0[8], R, acc0[t - 1])));
                        acc1[t - 1] = ff2(W1[6], L, ff2(W1[7], V, ff2(W1[8], R, acc1[t - 1])));
                    }
                    if (t >= 0 && t <= 7) {
                        acc0[t] = ff2(W0[3], L, ff2(W0[4], V, ff2(W0[5], R, acc0[t])));
                        acc1[t] = ff2(W1[3], L, ff2(W1[4], V, ff2(W1[5], R, acc1[t])));
                    }
                    if (t <= 6) {
                        acc0[t + 1] = ff2(W0[0], L, ff2(W0[1], V, ff2(W0[2], R, acc0[t + 1])));
                        acc1[t + 1] = ff2(W1[0], L, ff2(W1[1], V, ff2(W1[2], R, acc1[t + 1])));
                    }
                }
            }
        }

        #pragma unroll
        for (int j = 0; j < 4; j++) {
            float2 a = upk2(acc0[2 * j]);
            float2 c = upk2(acc0[2 * j + 1]);
            float v00 = fmaxf(fmaf(a.x, inv0, sh0), 0.f);
            float v01 = fmaxf(fmaf(a.y, inv0, sh0), 0.f);
            float v10 = fmaxf(fmaf(c.x, inv0, sh0), 0.f);
            float v11 = fmaxf(fmaf(c.y, inv0, sh0), 0.f);
            ob[oc0 * 256 + (4 * h + j) * 16 + iter * 4 + cp] =
                fmaxf(fmaxf(v00, v01), fmaxf(v10, v11));
            float2 a1 = upk2(acc1[2 * j]);
            float2 c1 = upk2(acc1[2 * j + 1]);
            float w00 = fmaxf(fmaf(a1.x, inv1, sh1), 0.f);
            float w01 = fmaxf(fmaf(a1.y, inv1, sh1), 0.f);
            float w10 = fmaxf(fmaf(c1.x, inv1, sh1), 0.f);
            float w11 = fmaxf(fmaf(c1.y, inv1, sh1), 0.f);
            ob[(oc0 + 1) * 256 + (4 * h + j) * 16 + iter * 4 + cp] =
                fmaxf(fmaxf(w00, w01), fmaxf(w10, w11));
        }
    }
}

// =============================================================================
// Stage 2 (R12 version — best measured ~766us): conv(32->64) + BN + ReLU +
// pool. grid=B*4, block=128. Dual-copy input rows (copyA [0,v..,0] at +0,
// copyB at +20, stride 40): L,V,R all aligned LDS.64, zero packs. Packed-ull
// weights staged per 8-ic pass (stride 73, bank-clean).
// =============================================================================
__global__ __launch_bounds__(128) void conv2_kernel(
    const float* __restrict__ bias,
    const float* __restrict__ gam,
    const float* __restrict__ bet,
    const float* __restrict__ mean,
    const float* __restrict__ var)
{
    __shared__ float s_in[8 * 16 * 40];   // 20 KB
    __shared__ ull   s_w[16 * 73];        // 9.3 KB

    const int b = blockIdx.x >> 2;
    const int oc_base = (blockIdx.x & 3) * 16;
    const int tid = threadIdx.x;
    const int warp = tid >> 5;
    const int lane = tid & 31;
    const int cp = lane & 7;             // col pair 0..7
    const int ocg = lane >> 3;           // 0..3
    const int h = warp >> 1;             // row half
    const int st = warp & 1;             // oc set
    const int oc0l = st * 8 + ocg * 2;
    const int oc0 = oc_base + oc0l;

    {
        int ic = tid >> 4, r = tid & 15;
        s_in[ic * 640 + r * 40] = 0.f;
        s_in[ic * 640 + r * 40 + 17] = 0.f;
    }

    ull acc0[8], acc1[8];
    #pragma unroll
    for (int i = 0; i < 8; i++) { acc0[i] = 0ull; acc1[i] = 0ull; }

    for (int pass = 0; pass < 4; pass++) {
        __syncthreads();
        {
            const float4* src = (const float4*)(g_h1 + (size_t)b * 8192 + pass * 2048);
            #pragma unroll
            for (int i = 0; i < 4; i++) {
                int idx4 = tid + i * 128;          // 0..511
                float4 v = src[idx4];
                int ic = idx4 >> 6;
                int r = (idx4 >> 2) & 15;
                int c4 = (idx4 & 3) * 4;
                float* row = &s_in[ic * 640 + r * 40];
                row[1 + c4] = v.x; row[2 + c4] = v.y;
                row[3 + c4] = v.z; row[4 + c4] = v.w;
                *(float4*)(row + 20 + c4) = v;
            }
        }
        for (int i = tid; i < 16 * 72; i += 128) {
            int o = i / 72, j = i % 72;
            s_w[o * 73 + j] = g_pw2[(oc_base + o) * 288 + pass * 72 + j];
        }
        __syncthreads();

        #pragma unroll 1
        for (int ici = 0; ici < 8; ici++) {
            const ull* w0p = &s_w[oc0l * 73 + ici * 9];
            const ull* w1p = w0p + 73;
            ull W0[9], W1[9];
            #pragma unroll
            for (int k = 0; k < 9; k++) { W0[k] = w0p[k]; W1[k] = w1p[k]; }

            const float* rb = &s_in[ici * 640 + 2 * cp];
            if (h == 0) {
                #pragma unroll
                for (int r = 0; r < 9; r++) {
                    ull L = *(const ull*)(rb + r * 40);
                    ull R = *(const ull*)(rb + r * 40 + 2);
                    ull V = *(const ull*)(rb + r * 40 + 20);
                    if (r >= 1) {
                        acc0[r - 1] = ff2(W0[6], L, ff2(W0[7], V, ff2(W0[8], R, acc0[r - 1])));
                        acc1[r - 1] = ff2(W1[6], L, ff2(W1[7], V, ff2(W1[8], R, acc1[r - 1])));
                    }
                    if (r <= 7) {
                        acc0[r] = ff2(W0[3], L, ff2(W0[4], V, ff2(W0[5], R, acc0[r])));
                        acc1[r] = ff2(W1[3], L, ff2(W1[4], V, ff2(W1[5], R, acc1[r])));
                    }
                    if (r <= 6) {
                        acc0[r + 1] = ff2(W0[0], L, ff2(W0[1], V, ff2(W0[2], R, acc0[r + 1])));
                        acc1[r + 1] = ff2(W1[0], L, ff2(W1[1], V, ff2(W1[2], R, acc1[r + 1])));
                    }
                }
            } else {
                #pragma unroll
                for (int ri = 0; ri < 9; ri++) {
                    const int r = 7 + ri;          // global in row
                    const int t = ri - 1;          // local out base
                    ull L = *(const ull*)(rb + r * 40);
                    ull R = *(const ull*)(rb + r * 40 + 2);
                    ull V = *(const ull*)(rb + r * 40 + 20);
                    if (t >= 1) {
                        acc0[t - 1] = ff2(W0[6], L, ff2(W0[7], V, ff2(W0[8], R, acc0[t - 1])));
                        acc1[t - 1] = ff2(W1[6], L, ff2(W1[7], V, ff2(W1[8], R, acc1[t - 1])));
                    }
                    if (t >= 0 && t <= 7) {
                        acc0[t] = ff2(W0[3], L, ff2(W0[4], V, ff2(W0[5], R, acc0[t])));
                        acc1[t] = ff2(W1[3], L, ff2(W1[4], V, ff2(W1[5], R, acc1[t])));
                    }
                    if (t <= 6) {
                        acc0[t + 1] = ff2(W0[0], L, ff2(W0[1], V, ff2(W0[2], R, acc0[t + 1])));
                        acc1[t + 1] = ff2(W1[0], L, ff2(W1[1], V, ff2(W1[2], R, acc1[t + 1])));
                    }
                }
            }
        }
    }

    #pragma unroll
    for (int k = 0; k < 2; k++) {
        const int oc = oc0 + k;
        const ull* ac = k ? acc1 : acc0;
        float inv = gam[oc] * rsqrtf(var[oc] + BN_EPS);
        float sh = (bias[oc] - mean[oc]) * inv + bet[oc];
        float* ob = g_h2 + (size_t)b * 4096 + (size_t)oc * 64 + cp;
        #pragma unroll
        for (int j = 0; j < 4; j++) {
            float2 a = upk2(ac[2 * j]);
            float2 c = upk2(ac[2 * j + 1]);
            float v00 = fmaxf(fmaf(a.x, inv, sh), 0.f);
            float v01 = fmaxf(fmaf(a.y, inv, sh), 0.f);
            float v10 = fmaxf(fmaf(c.x, inv, sh), 0.f);
            float v11 = fmaxf(fmaf(c.y, inv, sh), 0.f);
            ob[(h * 4 + j) * 8] = fmaxf(fmaxf(v00, v01), fmaxf(v10, v11));
        }
    }
}

// =============================================================================
// Stage 3 (R13 version — best measured 898us): conv(64->128) + BN + ReLU +
// pool + avgpool. grid=B*2, block=128 (4 warps x 16 oc). Single bordered
// input copy stride 12; V = pk2(L.y,R.x). FLOAT weights staged in 8-ic
// stages (stride 73, bank-clean); in-loop pk2 duplication.
// =============================================================================
__global__ __launch_bounds__(128) void conv3_kernel(
    const float* __restrict__ w3,    // [128,64,3,3]
    const float* __restrict__ bias,
    const float* __restrict__ gam,
    const float* __restrict__ bet,
    const float* __restrict__ mean,
    const float* __restrict__ var)
{
    __shared__ float s_in[32 * 96];    // 12.3 KB: ic*96 + r*12 + [0,v..,0]
    __shared__ float s_w[64 * 73];     // 18.7 KB

    const int b = blockIdx.x >> 1;
    const int oc_base = (blockIdx.x & 1) * 64;
    const int tid = threadIdx.x;
    const int warp = tid >> 5;
    const int lane = tid & 31;
    const int cp = lane & 3;             // col pair 0..3
    const int ocg = lane >> 2;           // 0..7
    const int oc0l = warp * 16 + ocg * 2;   // local 0..62
    const int oc0 = oc_base + oc0l;

    for (int i = tid; i < 256; i += 128) {
        int ic = i >> 3, r = i & 7;
        s_in[ic * 96 + r * 12] = 0.f;
        s_in[ic * 96 + r * 12 + 9] = 0.f;
    }

    ull acc0[8], acc1[8];
    #pragma unroll
    for (int i = 0; i < 8; i++) { acc0[i] = 0ull; acc1[i] = 0ull; }

    for (int pass = 0; pass < 2; pass++) {
        __syncthreads();
        {
            const float4* src = (const float4*)(g_h2 + (size_t)b * 4096 + pass * 2048);
            #pragma unroll
            for (int i = 0; i < 4; i++) {
                int idx4 = tid + i * 128;           // 0..511
                float4 v = src[idx4];
                int ic = idx4 >> 4;
                int r = (idx4 >> 1) & 7;
                int c4 = (idx4 & 1) * 4;
                float* row = &s_in[ic * 96 + r * 12];
                row[1 + c4] = v.x; row[2 + c4] = v.y;
                row[3 + c4] = v.z; row[4 + c4] = v.w;
            }
        }

        for (int ws = 0; ws < 4; ws++) {
            __syncthreads();
            for (int i = tid; i < 64 * 72; i += 128) {
                int o = i / 72, j = i % 72;
                s_w[o * 73 + j] =
                    w3[(size_t)(oc_base + o) * 576 + (pass * 32 + ws * 8) * 9 + j];
            }
            __syncthreads();

            #pragma unroll 1
            for (int ici = 0; ici < 8; ici++) {
                const int icl = ws * 8 + ici;     // 0..31 within pass
                const float* wq0 = &s_w[oc0l * 73 + ici * 9];
                const float* wq1 = wq0 + 73;
                ull W0[9], W1[9];
                #pragma unroll
                for (int k = 0; k < 9; k++) {
                    float a = wq0[k], c_ = wq1[k];
                    W0[k] = pk2(a, a); W1[k] = pk2(c_, c_);
                }

                const float* rb = &s_in[icl * 96 + 2 * cp];
                #pragma unroll
                for (int r = 0; r < 8; r++) {
                    ull L = *(const ull*)(rb + r * 12);
                    ull R = *(const ull*)(rb + r * 12 + 2);
                    float2 Lf = upk2(L), Rf = upk2(R);
                    ull V = pk2(Lf.y, Rf.x);
                    if (r >= 1) {
                        acc0[r - 1] = ff2(W0[6], L, ff2(W0[7], V, ff2(W0[8], R, acc0[r - 1])));
                        acc1[r - 1] = ff2(W1[6], L, ff2(W1[7], V, ff2(W1[8], R, acc1[r - 1])));
                    }
                    acc0[r] = ff2(W0[3], L, ff2(W0[4], V, ff2(W0[5], R, acc0[r])));
                    acc1[r] = ff2(W1[3], L, ff2(W1[4], V, ff2(W1[5], R, acc1[r])));
                    if (r <= 6) {
                        acc0[r + 1] = ff2(W0[0], L, ff2(W0[1], V, ff2(W0[2], R, acc0[r + 1])));
                        acc1[r + 1] = ff2(W1[0], L, ff2(W1[1], V, ff2(W1[2], R, acc1[r + 1])));
                    }
                }
            }
        }
    }

    #pragma unroll
    for (int k = 0; k < 2; k++) {
        const int oc = oc0 + k;
        const ull* ac = k ? acc1 : acc0;
        float inv = gam[oc] * rsqrtf(var[oc] + BN_EPS);
        float sh = (bias[oc] - mean[oc]) * inv + bet[oc];
        float sum = 0.f;
        #pragma unroll
        for (int j = 0; j < 4; j++) {
            float2 a = upk2(ac[2 * j]);
            float2 c = upk2(ac[2 * j + 1]);
            float v00 = fmaxf(fmaf(a.x, inv, sh), 0.f);
            float v01 = fmaxf(fmaf(a.y, inv, sh), 0.f);
            float v10 = fmaxf(fmaf(c.x, inv, sh), 0.f);
            float v11 = fmaxf(fmaf(c.y, inv, sh), 0.f);
            sum += fmaxf(fmaxf(v00, v01), fmaxf(v10, v11));
        }
        sum += __shfl_down_sync(0xffffffffu, sum, 2, 4);
        sum += __shfl_down_sync(0xffffffffu, sum, 1, 4);
        if (cp == 0)
            g_feat[(size_t)b * 128 + oc] = sum * (1.f / 16.f);
    }
}

// =============================================================================
// Stage 4: gate (top-2 softmax) + top-2 expert MLPs, fused. (unchanged, 55us)
// =============================================================================
__global__ __launch_bounds__(256) void moe_kernel(
    const float* __restrict__ w1,   // [8,128,64]
    const float* __restrict__ b1,   // [8,64]
    const float* __restrict__ w2,   // [8,64,10]
    const float* __restrict__ b2,   // [8,10]
    const float* __restrict__ gw,   // [128,8]
    const float* __restrict__ gb,   // [8]
    float* __restrict__ out, int B)
{
    __shared__ float s_feat[8][128];
    __shared__ float s_h[8][64];
    __shared__ float s_log[8][8];

    const int warp = threadIdx.x >> 5;
    const int lane = threadIdx.x & 31;
    const int s = blockIdx.x * 8 + warp;
    if (s >= B) return;

    for (int i = lane; i < 128; i += 32) s_feat[warp][i] = g_feat[(size_t)s * 128 + i];
    __syncwarp();

    if (lane < 8) {
        float a = gb[lane];
        for (int f = 0; f < 128; f++) a += s_feat[warp][f] * gw[f * 8 + lane];
        s_log[warp][lane] = a;
    }
    __syncwarp();

    float lg[8];
    #pragma unroll
    for (int e = 0; e < 8; e++) lg[e] = s_log[warp][e];
    int i0 = 0; float v0 = lg[0];
    #pragma unroll
    for (int e = 1; e < 8; e++) if (lg[e] > v0) { v0 = lg[e]; i0 = e; }
    int i1 = -1; float v1 = -3.402823466e38f;
    #pragma unroll
    for (int e = 0; e < 8; e++) if (e != i0 && lg[e] > v1) { v1 = lg[e]; i1 = e; }
    float e1 = expf(v1 - v0);
    float invs = 1.f / (1.f + e1);
    float wts[2] = { invs, e1 * invs };
    int eidx[2] = { i0, i1 };

    float outk = 0.f;
    for (int t = 0; t < 2; t++) {
        const int e = eidx[t];
        const float* w1e = w1 + (size_t)e * 128 * 64;
        float h0 = b1[e * 64 + lane];
        float h1v = b1[e * 64 + lane + 32];
        for (int f = 0; f < 128; f++) {
            float fv = s_feat[warp][f];
            h0  += fv * w1e[f * 64 + lane];
            h1v += fv * w1e[f * 64 + lane + 32];
        }
        s_h[warp][lane] = fmaxf(h0, 0.f);
        s_h[warp][lane + 32] = fmaxf(h1v, 0.f);
        __syncwarp();
        if (lane < 10) {
            const float* w2e = w2 + e * 640;
            float o = b2[e * 10 + lane];
            for (int j = 0; j < 64; j++) o += s_h[warp][j] * w2e[j * 10 + lane];
            outk += wts[t] * o;
        }
        __syncwarp();
    }
    if (lane < 10) out[(size_t)s * 10 + lane] = outk;
}

// =============================================================================
extern "C" void kernel_launch(void* const* d_in, const int* in_sizes, int n_in,
                              void* d_out, int out_size)
{
    const float* x       = (const float*)d_in[0];
    const float* c1w     = (const float*)d_in[1];
    const float* c1b     = (const float*)d_in[2];
    const float* bn1g    = (const float*)d_in[3];
    const float* bn1b    = (const float*)d_in[4];
    const float* bn1m    = (const float*)d_in[5];
    const float* bn1v    = (const float*)d_in[6];
    const float* c2w     = (const float*)d_in[7];
    const float* c2b     = (const float*)d_in[8];
    const float* bn2g    = (const float*)d_in[9];
    const float* bn2b    = (const float*)d_in[10];
    const float* bn2m    = (const float*)d_in[11];
    const float* bn2v    = (const float*)d_in[12];
    const float* c3w     = (const float*)d_in[13];
    const float* c3b     = (const float*)d_in[14];
    const float* bn3g    = (const float*)d_in[15];
    const float* bn3b    = (const float*)d_in[16];
    const float* bn3m    = (const float*)d_in[17];
    const float* bn3v    = (const float*)d_in[18];
    const float* w1      = (const float*)d_in[19];
    const float* b1      = (const float*)d_in[20];
    const float* w2      = (const float*)d_in[21];
    const float* b2      = (const float*)d_in[22];
    const float* gate_w  = (const float*)d_in[23];
    const float* gate_b  = (const float*)d_in[24];

    int B = in_sizes[0] / (3 * 32 * 32);
    if (B > 4096) B = 4096;

    // prep kernel doubles as launch-slot shifter: profiled slot = conv3
    prep_pack_kernel<<<80, 256>>>(c1w, c2w);
    conv1_kernel<<<B * 2, 128>>>(x, c1b, bn1g, bn1b, bn1m, bn1v);
    conv2_kernel<<<B * 4, 128>>>(c2b, bn2g, bn2b, bn2m, bn2v);
    conv3_kernel<<<B * 2, 128>>>(c3w, c3b, bn3g, bn3b, bn3m, bn3v);
    moe_kernel<<<(B + 7) / 8, 256>>>(w1, b1, w2, b2, gate_w, gate_b, (float*)d_out, B);
}